// round 11
// baseline (speedup 1.0000x reference)
#include <cuda_runtime.h>

#define CC 192
#define HW_ 9216
#define PSTRIDE 59   // 33 softplus(mat) + 13 bias + 13 tanh(factor)

__device__ __forceinline__ float fast_sigmoid(float x) {
    float e = __expf(-x);
    return __fdividef(1.0f, 1.0f + e);
}

__device__ __forceinline__ float fast_tanh(float x) {
    float y;
    asm("tanh.approx.f32 %0, %1;" : "=f"(y) : "f"(x));
    return y;
}

__device__ __forceinline__ float softplus_fast(float x) {
    return (x > 15.0f) ? x : __logf(1.0f + __expf(x));
}

// -------------------------------------------------------------------------
// Generic slow logits (gated fallback only). Reads transformed params from
// shared; loop-kept so it never taxes fast-path registers.
// -------------------------------------------------------------------------
__device__ __noinline__ float logits_slow(const float* P, float t)
{
    float h[3];
#pragma unroll 1
    for (int i = 0; i < 3; i++) {
        float g = fmaf(P[i], t, P[33 + i]);
        h[i] = g + P[46 + i] * tanhf(g);
    }
#pragma unroll 1
    for (int l = 1; l < 4; l++) {
        const float* M = P + 3 + (l - 1) * 9;
        float g[3];
#pragma unroll 1
        for (int r = 0; r < 3; r++) {
            float s = P[33 + 3 * l + r];
#pragma unroll 1
            for (int k = 0; k < 3; k++) s = fmaf(M[3 * r + k], h[k], s);
            g[r] = s + P[46 + 3 * l + r] * tanhf(s);
        }
        h[0] = g[0]; h[1] = g[1]; h[2] = g[2];
    }
    float o = P[33 + 12];
#pragma unroll 1
    for (int k = 0; k < 3; k++) o = fmaf(P[30 + k], h[k], o);
    return o + P[46 + 12] * tanhf(o);
}

__device__ __forceinline__ float lk_from_LU(float L, float U)
{
    float su = L + U;
    float s = (su > 0.0f) ? -1.0f : ((su < 0.0f) ? 1.0f : 0.0f);  // -sign(L+U)
    float lk = fabsf(fast_sigmoid(s * U) - fast_sigmoid(s * L));
    return fmaxf(lk, 1e-9f);
}

// -------------------------------------------------------------------------
// Single fused kernel, v2. 256 thr x 4 elems = 1024/block (1024 | 9216 so
// each block is channel-uniform). Prologue is confined to WARP 0: its lanes
// transform the channel's 59 params into shared (syncwarp only), lane 0
// composes the affine collapse logits(t)=a*t+b (exact when all tanh gates
// are zero); then a single __syncthreads. Streaming __ldcs are issued
// before the prologue so they fly during it. launch_bounds(256,8) pins
// regs<=32 for 8 blocks/SM — the R6-proven occupancy.
// -------------------------------------------------------------------------
__global__ void __launch_bounds__(256, 8) eb_fused(
    const float4* __restrict__ x4, const float4* __restrict__ n4,
    float* __restrict__ out, int n4tot,
    const float* __restrict__ m0, const float* __restrict__ m1,
    const float* __restrict__ m2, const float* __restrict__ m3,
    const float* __restrict__ m4,
    const float* __restrict__ b0, const float* __restrict__ b1,
    const float* __restrict__ b2, const float* __restrict__ b3,
    const float* __restrict__ b4,
    const float* __restrict__ f0, const float* __restrict__ f1,
    const float* __restrict__ f2, const float* __restrict__ f3,
    const float* __restrict__ f4)
{
    __shared__ float S[PSTRIDE];
    __shared__ float Aa, Abm, Agate;

    // Streaming loads first — prologue hides under them.
    int i4 = blockIdx.x * 256 + threadIdx.x;
    float4 xv = __ldcs(x4 + i4);
    float4 nv = __ldcs(n4 + i4);

    int c = (blockIdx.x / 9) % CC;   // 1024 elems/block, 9216 = 9*1024 per channel

    if (threadIdx.x < 32) {
        int lane = threadIdx.x;
#pragma unroll
        for (int pass = 0; pass < 2; pass++) {
            int s = lane + pass * 32;
            if (s < PSTRIDE) {
                float val;
                if (s < 33) {
                    const float* ms[5] = {m0, m1, m2, m3, m4};
                    const int moff[5] = {0, 3, 12, 21, 30};
                    const int msz[5]  = {3, 9, 9, 9, 3};
                    int l = (s < 3) ? 0 : (s < 12) ? 1 : (s < 21) ? 2 : (s < 30) ? 3 : 4;
                    val = softplus_fast(ms[l][c * msz[l] + (s - moff[l])]);
                } else if (s < 46) {
                    const float* bs[5] = {b0, b1, b2, b3, b4};
                    const int uoff[5] = {0, 3, 6, 9, 12};
                    const int usz[5]  = {3, 3, 3, 3, 1};
                    int u = s - 33;
                    int l = (u < 3) ? 0 : (u < 6) ? 1 : (u < 9) ? 2 : (u < 12) ? 3 : 4;
                    val = bs[l][c * usz[l] + (u - uoff[l])];
                } else {
                    const float* fs[5] = {f0, f1, f2, f3, f4};
                    const int uoff[5] = {0, 3, 6, 9, 12};
                    const int usz[5]  = {3, 3, 3, 3, 1};
                    int u = s - 46;
                    int l = (u < 3) ? 0 : (u < 6) ? 1 : (u < 9) ? 2 : (u < 12) ? 3 : 4;
                    val = fast_tanh(fs[l][c * usz[l] + (u - uoff[l])]);
                }
                S[s] = val;
            }
        }
        __syncwarp();

        if (lane == 0) {
            const float* sp = S;
            const float* bb = S + 33;
            const float* tf = S + 46;

            bool gated = false;
#pragma unroll
            for (int i = 0; i < 13; i++) gated = gated || (tf[i] != 0.0f);

            float a0 = sp[0], a1 = sp[1], a2 = sp[2];
            float v0 = bb[0], v1 = bb[1], v2 = bb[2];
#pragma unroll
            for (int l = 1; l < 4; l++) {
                const float* M = sp + 3 + (l - 1) * 9;
                const float* B = bb + 3 * l;
                float na0 = M[0]*a0 + M[1]*a1 + M[2]*a2;
                float na1 = M[3]*a0 + M[4]*a1 + M[5]*a2;
                float na2 = M[6]*a0 + M[7]*a1 + M[8]*a2;
                float nv0 = M[0]*v0 + M[1]*v1 + M[2]*v2 + B[0];
                float nv1 = M[3]*v0 + M[4]*v1 + M[5]*v2 + B[1];
                float nv2 = M[6]*v0 + M[7]*v1 + M[8]*v2 + B[2];
                a0 = na0; a1 = na1; a2 = na2;
                v0 = nv0; v1 = nv1; v2 = nv2;
            }
            float a_s = sp[30]*a0 + sp[31]*a1 + sp[32]*a2;
            float b_s = sp[30]*v0 + sp[31]*v1 + sp[32]*v2 + bb[12];
            Aa = a_s;
            Abm = b_s - 0.5f * a_s;
            Agate = gated ? 1.0f : 0.0f;
        }
    }
    __syncthreads();

    float a = Aa, bm = Abm, gate = Agate;
    float4 v = make_float4(xv.x + nv.x, xv.y + nv.y, xv.z + nv.z, xv.w + nv.w);

    float4* o4 = (float4*)out;
    __stcs(o4 + i4, v);  // outputs = v

    float4 lk;
    if (gate == 0.0f) {
        float Lx = fmaf(a, v.x, bm), Ly = fmaf(a, v.y, bm);
        float Lz = fmaf(a, v.z, bm), Lw = fmaf(a, v.w, bm);
        lk.x = lk_from_LU(Lx, Lx + a);
        lk.y = lk_from_LU(Ly, Ly + a);
        lk.z = lk_from_LU(Lz, Lz + a);
        lk.w = lk_from_LU(Lw, Lw + a);
    } else {
        lk.x = lk_from_LU(logits_slow(S, v.x - 0.5f), logits_slow(S, v.x + 0.5f));
        lk.y = lk_from_LU(logits_slow(S, v.y - 0.5f), logits_slow(S, v.y + 0.5f));
        lk.z = lk_from_LU(logits_slow(S, v.z - 0.5f), logits_slow(S, v.z + 0.5f));
        lk.w = lk_from_LU(logits_slow(S, v.w - 0.5f), logits_slow(S, v.w + 0.5f));
    }
    __stcs(o4 + n4tot + i4, lk);  // likelihood
}

extern "C" void kernel_launch(void* const* d_in, const int* in_sizes, int n_in,
                              void* d_out, int out_size)
{
    const float* X  = (const float*)d_in[0];
    const float* NZ = (const float*)d_in[1];

    const float *m[5], *b[5], *f[5];
    if (in_sizes[3] == 3 * in_sizes[2]) {      // signature order
        for (int i = 0; i < 5; i++) {
            m[i] = (const float*)d_in[2 + i];
            b[i] = (const float*)d_in[7 + i];
            f[i] = (const float*)d_in[12 + i];
        }
    } else {                                   // dict order m,b,f interleaved
        for (int i = 0; i < 5; i++) {
            m[i] = (const float*)d_in[2 + 3 * i];
            b[i] = (const float*)d_in[3 + 3 * i];
            f[i] = (const float*)d_in[4 + 3 * i];
        }
    }

    int N = in_sizes[0];  // B*C*H*W = 28,311,552
    int blocks = N / 1024;  // 256 threads * 4 elems

    eb_fused<<<blocks, 256>>>(
        (const float4*)X, (const float4*)NZ, (float*)d_out, N / 4,
        m[0], m[1], m[2], m[3], m[4],
        b[0], b[1], b[2], b[3], b[4],
        f[0], f[1], f[2], f[3], f[4]);
}